// round 2
// baseline (speedup 1.0000x reference)
#include <cuda_runtime.h>
#include <math.h>

#define NUMR    100
#define BATCH   2048
#define NVAR    192
#define NEQC    30
#define NHDIM   222
#define MAXIT   15
#define SPB     8
#define NTHREADS 512

// shared memory float offsets
#define OFF_XT4  0        // 3*25*32 float4 = 9600 floats  (X transposed, r-chunked)
#define OFF_X4   9600     // 3*100*9 float4 = 10800 floats (X row-major, padded row=9 float4)
#define OFF_Y    20400    // SPB * 3 * 600 = 14400
#define OFF_W    34800    // SPB * 600 = 4800
#define OFF_RHS  39600    // SPB * 192
#define OFF_PRIM 41136    // SPB * 192
#define OFF_Q    42672    // 192 rows x 20 floats = 3840   ([j][k] tile, pad 20)
#define OFF_RED  46512    // 16 warps * 12
#define SMEM_FLOATS 46704 // 186,816 bytes

__device__ __forceinline__ float dot4(float4 a, float4 b) {
    return a.x*b.x + a.y*b.y + a.z*b.z + a.w*b.w;
}

__global__ void __launch_bounds__(NTHREADS, 1)
proj_filter_kernel(const float* __restrict__ lamda,
                   const float* __restrict__ c_in_g,
                   const float* __restrict__ c_samp,
                   const float* __restrict__ b_eq,
                   const float* __restrict__ Av,
                   const float* __restrict__ Aa,
                   const float* __restrict__ Ap,
                   const float* __restrict__ Qi,
                   float* __restrict__ out)
{
    extern __shared__ float sm[];
    const int tid   = threadIdx.x;
    const int warp  = tid >> 5;
    const int lane  = tid & 31;
    const int samp  = warp >> 1;     // 0..7 sample within CTA
    const int h     = warp & 1;      // half: owns dofs 3h..3h+2
    const int mb    = 3 * h;
    const int s     = blockIdx.x * SPB + samp;

    // ---- stage X matrices (top-left 100x32 block of each kron'd A) ----
    for (int idx = tid; idx < 3 * NUMR * 32; idx += NTHREADS) {
        int t   = idx / (NUMR * 32);
        int rem = idx - t * (NUMR * 32);
        int r = rem >> 5;
        int c = rem & 31;
        const float* Asrc = (t == 0) ? Av : ((t == 1) ? Aa : Ap);
        float v = Asrc[r * NVAR + c];
        sm[OFF_XT4 + ((t * 25 + (r >> 2)) * 32 + c) * 4 + (r & 3)] = v;
        sm[OFF_X4 + ((t * NUMR + r) * 9 + (c >> 2)) * 4 + (c & 3)] = v;
    }

    const float Vb[3] = {0.8f, 1.8f, 3.14159265358979323846f};

    const int yb    = OFF_Y    + samp * 1800;
    const int wb    = OFF_W    + samp * 600;
    const int rbase = OFF_RHS  + samp * 192;
    const int pbase = OFF_PRIM + samp * 192;

    // ---- per-sample per-half register state (own 3 dofs) ----
    float cin[3], cprev[3], pbv[3], l[3][3];
#pragma unroll
    for (int m = 0; m < 3; m++) {
        int j = (mb + m) * 32 + lane;
        cin[m]   = c_in_g[s * NVAR + j];
        cprev[m] = c_samp[s * NVAR + j];
    }
#pragma unroll
    for (int t = 0; t < 3; t++)
#pragma unroll
        for (int m = 0; m < 3; m++)
            l[t][m] = lamda[s * (3 * NVAR) + t * NVAR + (mb + m) * 32 + lane];

    // pb = Q_inv[:192,192:222] @ b_eq   (iteration-invariant)
#pragma unroll
    for (int m = 0; m < 3; m++) {
        float a = 0.f;
        int j = (mb + m) * 32 + lane;
        for (int k = 0; k < NEQC; k++)
            a += Qi[j * NHDIM + NVAR + k] * b_eq[s * NEQC + k];
        pbv[m] = a;
    }

    // ---- stage initial primal guess, init y = c_samples @ X^T (own dofs) ----
#pragma unroll
    for (int m = 0; m < 3; m++) sm[pbase + (mb + m) * 32 + lane] = cprev[m];
    __syncthreads();   // X staged + pbase staged

    for (int t = 0; t < 3; t++) {
#pragma unroll
        for (int k = 0; k < 4; k++) {
            int rr = lane + 32 * k;
            if (rr < NUMR) {
                const float4* xr = (const float4*)&sm[OFF_X4] + (t * NUMR + rr) * 9;
                float4 x0 = xr[0], x1 = xr[1], x2 = xr[2], x3 = xr[3];
                float4 x4 = xr[4], x5 = xr[5], x6 = xr[6], x7 = xr[7];
#pragma unroll
                for (int m = 0; m < 3; m++) {
                    int d = mb + m;
                    const float4* pp = (const float4*)&sm[pbase] + d * 8;
                    float a = dot4(x0, pp[0]) + dot4(x1, pp[1]) + dot4(x2, pp[2]) + dot4(x3, pp[3])
                            + dot4(x4, pp[4]) + dot4(x5, pp[5]) + dot4(x6, pp[6]) + dot4(x7, pp[7]);
                    sm[yb + t * 600 + d * NUMR + rr] = a;
                }
            }
        }
    }
    __syncwarp();

    float fp_sum = 0.f, rp_sum = 0.f;

    // precompute phase-B staging indices (3 float2 per thread per tile)
    int bj[3], bp[3];
#pragma unroll
    for (int r = 0; r < 3; r++) {
        int e = tid + r * NTHREADS;   // 0..1535
        bj[r] = e >> 3;               // row j
        bp[r] = e & 7;                // float2 pair within 16 k's
    }

    for (int it = 0; it < MAXIT; it++) {
        // ======== phase A: rhs = lv+la+lp+cin + sum_t u_t @ X_t  (own dofs) ========
        float acc[3];
#pragma unroll
        for (int m = 0; m < 3; m++) acc[m] = l[0][m] + l[1][m] + l[2][m] + cin[m];

        for (int t = 0; t < 3; t++) {
            float V = Vb[t];
#pragma unroll
            for (int i = lane; i < 300; i += 32) {
                int gi = h * 300 + i;
                float y = sm[yb + t * 600 + gi];
                sm[wb + gi] = fminf(V, y) - fminf(V, -y);
            }
            __syncwarp();
            const float4* XT = (const float4*)&sm[OFF_XT4] + t * 25 * 32;
            const float4* W4 = (const float4*)&sm[wb];
#pragma unroll
            for (int rbk = 0; rbk < 25; rbk++) {
                float4 xt = XT[rbk * 32 + lane];
#pragma unroll
                for (int m = 0; m < 3; m++)
                    acc[m] += dot4(xt, W4[(mb + m) * 25 + rbk]);
            }
            __syncwarp();
        }
#pragma unroll
        for (int m = 0; m < 3; m++) sm[rbase + (mb + m) * 32 + lane] = acc[m];
        __syncthreads();

        // ======== phase B: primal = Q_inv[:192,:192] @ rhs + pb ========
        float pr[3];
#pragma unroll
        for (int m = 0; m < 3; m++) pr[m] = pbv[m];

        // prefetch tile kc=0
        float2 pf[3];
#pragma unroll
        for (int r = 0; r < 3; r++)
            pf[r] = *(const float2*)(Qi + bj[r] * NHDIM + 2 * bp[r]);

        for (int kc = 0; kc < 12; kc++) {
            // tile buffer free here (consumers of previous tile passed a barrier)
#pragma unroll
            for (int r = 0; r < 3; r++)
                *(float2*)&sm[OFF_Q + bj[r] * 20 + 2 * bp[r]] = pf[r];
            if (kc < 11) {
#pragma unroll
                for (int r = 0; r < 3; r++)
                    pf[r] = *(const float2*)(Qi + bj[r] * NHDIM + (kc + 1) * 16 + 2 * bp[r]);
            }
            __syncthreads();   // tile ready
            const float4* Qt4 = (const float4*)&sm[OFF_Q];
            const float4* RV  = (const float4*)&sm[rbase + kc * 16];
#pragma unroll
            for (int g = 0; g < 4; g++) {
                float4 rv = RV[g];
#pragma unroll
                for (int m = 0; m < 3; m++) {
                    int j = (mb + m) * 32 + lane;
                    pr[m] += dot4(Qt4[j * 5 + g], rv);
                }
            }
            __syncthreads();   // all consumed before overwrite
        }

        // ======== phase C: y update, residuals, lambda updates (own dofs) ========
#pragma unroll
        for (int m = 0; m < 3; m++) sm[pbase + (mb + m) * 32 + lane] = pr[m];
        float dc = 0.f;
#pragma unroll
        for (int m = 0; m < 3; m++) {
            float dd = pr[m] - cprev[m];
            dc += dd * dd;
            cprev[m] = pr[m];
        }
        __syncthreads();   // full primal ready

        float resn[3], dsn[3], dln[3];
        for (int t = 0; t < 3; t++) {
            float V = Vb[t];
            float ra = 0.f, da = 0.f;
#pragma unroll
            for (int k = 0; k < 4; k++) {
                int rr = lane + 32 * k;
                if (rr < NUMR) {
                    const float4* xr = (const float4*)&sm[OFF_X4] + (t * NUMR + rr) * 9;
                    float4 x0 = xr[0], x1 = xr[1], x2 = xr[2], x3 = xr[3];
                    float4 x4 = xr[4], x5 = xr[5], x6 = xr[6], x7 = xr[7];
#pragma unroll
                    for (int m = 0; m < 3; m++) {
                        int d = mb + m;
                        const float4* pp = (const float4*)&sm[pbase] + d * 8;
                        float yn = dot4(x0, pp[0]) + dot4(x1, pp[1]) + dot4(x2, pp[2]) + dot4(x3, pp[3])
                                 + dot4(x4, pp[4]) + dot4(x5, pp[5]) + dot4(x6, pp[6]) + dot4(x7, pp[7]);
                        int i = t * 600 + d * NUMR + rr;
                        float yo = sm[yb + i];
                        float rt  = fmaxf(yn - V, 0.f);
                        float rbm = fmaxf(-yn - V, 0.f);
                        ra += rt * rt + rbm * rbm;
                        float d1 = fmaxf(V - yn, 0.f) - fmaxf(V - yo, 0.f);
                        float d2 = fmaxf(V + yn, 0.f) - fmaxf(V + yo, 0.f);
                        da += d1 * d1 + d2 * d2;
                        sm[yb + i] = yn;
                        sm[wb + d * NUMR + rr] = rt - rbm;
                    }
                }
            }
            resn[t] = ra;
            dsn[t]  = da;
            __syncwarp();
            // lambda update: dl = w @ X (own dofs)
            float dl[3] = {0.f, 0.f, 0.f};
            const float4* XT = (const float4*)&sm[OFF_XT4] + t * 25 * 32;
            const float4* W4 = (const float4*)&sm[wb];
#pragma unroll
            for (int rbk = 0; rbk < 25; rbk++) {
                float4 xt = XT[rbk * 32 + lane];
#pragma unroll
                for (int m = 0; m < 3; m++)
                    dl[m] += dot4(xt, W4[(mb + m) * 25 + rbk]);
            }
            float dls = 0.f;
#pragma unroll
            for (int m = 0; m < 3; m++) {
                l[t][m] -= dl[m];
                dls += dl[m] * dl[m];
            }
            dln[t] = dls;
            __syncwarp();
        }

        // intra-warp reduce of 10 partial squared norms
        float red[10] = {resn[0], resn[1], resn[2],
                         dsn[0],  dsn[1],  dsn[2],
                         dln[0],  dln[1],  dln[2], dc};
#pragma unroll
        for (int off = 16; off; off >>= 1)
#pragma unroll
            for (int q = 0; q < 10; q++)
                red[q] += __shfl_xor_sync(0xffffffffu, red[q], off);

        if (lane == 0) {
#pragma unroll
            for (int q = 0; q < 10; q++)
                sm[OFF_RED + warp * 12 + q] = red[q];
        }
        __syncthreads();
        {
            int wp = warp ^ 1;
            float tot[10];
#pragma unroll
            for (int q = 0; q < 10; q++)
                tot[q] = sm[OFF_RED + warp * 12 + q] + sm[OFF_RED + wp * 12 + q];
            rp_sum += sqrtf(tot[0]) + sqrtf(tot[1]) + sqrtf(tot[2]);
            fp_sum += sqrtf(tot[3]) + sqrtf(tot[4]) + sqrtf(tot[5])
                    + sqrtf(tot[6]) + sqrtf(tot[7]) + sqrtf(tot[8]) + sqrtf(tot[9]);
        }
        __syncthreads();
    }

    // ---- outputs: [c_out (B,192)] [avg_res_fixed_point (B)] [avg_res_primal (B)] ----
#pragma unroll
    for (int m = 0; m < 3; m++)
        out[s * NVAR + (mb + m) * 32 + lane] = cprev[m];
    if (h == 0 && lane == 0) {
        out[BATCH * NVAR + s]         = fp_sum * (1.0f / MAXIT);
        out[BATCH * NVAR + BATCH + s] = rp_sum * (1.0f / MAXIT);
    }
}

extern "C" void kernel_launch(void* const* d_in, const int* in_sizes, int n_in,
                              void* d_out, int out_size)
{
    const float* lamda = (const float*)d_in[0];
    const float* c_in  = (const float*)d_in[1];
    const float* c_s   = (const float*)d_in[2];
    const float* b_eq  = (const float*)d_in[3];
    const float* Av    = (const float*)d_in[4];
    const float* Aa    = (const float*)d_in[5];
    const float* Ap    = (const float*)d_in[6];
    const float* Qi    = (const float*)d_in[7];
    float* out = (float*)d_out;

    int smem_bytes = SMEM_FLOATS * sizeof(float);
    cudaFuncSetAttribute(proj_filter_kernel,
                         cudaFuncAttributeMaxDynamicSharedMemorySize, smem_bytes);
    proj_filter_kernel<<<BATCH / SPB, NTHREADS, smem_bytes>>>(
        lamda, c_in, c_s, b_eq, Av, Aa, Ap, Qi, out);
}

// round 3
// speedup vs baseline: 1.0863x; 1.0863x over previous
#include <cuda_runtime.h>
#include <math.h>

#define NUMR    100
#define BATCH   2048
#define NVAR    192
#define NEQC    30
#define NHDIM   222
#define MAXIT   15
#define SPB     8
#define NTHREADS 512

// shared memory float offsets
#define OFF_XT4  0        // 3*25*32 float4 = 9600 floats (X transposed, r-chunked)
#define OFF_X4   9600     // 3*100*9 float4 = 10800 floats (X row-major, 36-float row stride)
#define OFF_Y    20400    // SPB * 3 * 600 = 14400
#define OFF_W    34800    // SPB * 600 = 4800
#define OFF_RHS  39600    // SPB * 200 = 1600  (192 used, pad 200)
#define OFF_PRIM 41200    // SPB * 200 = 1600
#define OFF_Q    42800    // 192 * 36 = 6912   (32-k tile, 36-float row stride)
#define OFF_RED  49712    // 16 warps * 12
#define SMEM_FLOATS 49904 // 199,616 bytes

typedef unsigned long long ull;

__device__ __forceinline__ void fma2(ull& d, ull a, ull b) {
    asm("fma.rn.f32x2 %0, %1, %2, %0;" : "+l"(d) : "l"(a), "l"(b));
}
__device__ __forceinline__ float hadd2(ull v) {
    float lo, hi;
    asm("mov.b64 {%0, %1}, %2;" : "=f"(lo), "=f"(hi) : "l"(v));
    return lo + hi;
}
__device__ __forceinline__ float hadd2x2(ull a, ull b) {
    return hadd2(a) + hadd2(b);
}

__global__ void __launch_bounds__(NTHREADS, 1)
proj_filter_kernel(const float* __restrict__ lamda,
                   const float* __restrict__ c_in_g,
                   const float* __restrict__ c_samp,
                   const float* __restrict__ b_eq,
                   const float* __restrict__ Av,
                   const float* __restrict__ Aa,
                   const float* __restrict__ Ap,
                   const float* __restrict__ Qi,
                   float* __restrict__ out)
{
    extern __shared__ float sm[];
    const int tid   = threadIdx.x;
    const int warp  = tid >> 5;
    const int lane  = tid & 31;
    const int samp  = warp >> 1;     // 0..7 sample within CTA
    const int h     = warp & 1;      // half: owns dofs 3h..3h+2
    const int mb    = 3 * h;
    const int s     = blockIdx.x * SPB + samp;

    // phase-B role: warp owns Q rows [warp*12, warp*12+12); lane = (r4, s8)
    const int bs  = lane & 7;                 // sample 0..7
    const int br  = lane >> 3;                // 0..3
    const int bj0 = warp * 12 + br;           // + jg*4

    // ---- stage X matrices (top-left 100x32 block of each kron'd A) ----
    for (int idx = tid; idx < 3 * NUMR * 32; idx += NTHREADS) {
        int t   = idx / (NUMR * 32);
        int rem = idx - t * (NUMR * 32);
        int r = rem >> 5;
        int c = rem & 31;
        const float* Asrc = (t == 0) ? Av : ((t == 1) ? Aa : Ap);
        float v = Asrc[r * NVAR + c];
        sm[OFF_XT4 + ((t * 25 + (r >> 2)) * 32 + c) * 4 + (r & 3)] = v;
        sm[OFF_X4 + (t * NUMR + r) * 36 + c] = v;
    }

    const float Vb[3] = {0.8f, 1.8f, 3.14159265358979323846f};

    const int yb    = OFF_Y    + samp * 1800;
    const int wb    = OFF_W    + samp * 600;
    const int rbase = OFF_RHS  + samp * 200;
    const int pbase = OFF_PRIM + samp * 200;

    // ---- per-sample per-half register state (own 3 dofs) ----
    float cin[3], cprev[3], l[3][3];
#pragma unroll
    for (int m = 0; m < 3; m++) {
        int j = (mb + m) * 32 + lane;
        cin[m]   = c_in_g[s * NVAR + j];
        cprev[m] = c_samp[s * NVAR + j];
    }
#pragma unroll
    for (int t = 0; t < 3; t++)
#pragma unroll
        for (int m = 0; m < 3; m++)
            l[t][m] = lamda[s * (3 * NVAR) + t * NVAR + (mb + m) * 32 + lane];

    // pb[jg] = Q_inv[j,192:222] @ b_eq[bs]   (iteration-invariant, phase-B role)
    float pbq[3];
#pragma unroll
    for (int jg = 0; jg < 3; jg++) {
        int j = bj0 + jg * 4;
        float a = 0.f;
        const float* bq = b_eq + (blockIdx.x * SPB + bs) * NEQC;
        for (int k = 0; k < NEQC; k++)
            a += Qi[j * NHDIM + NVAR + k] * bq[k];
        pbq[jg] = a;
    }

    // ---- stage initial primal guess, init y = c_samples @ X^T (own dofs) ----
#pragma unroll
    for (int m = 0; m < 3; m++) sm[pbase + (mb + m) * 32 + lane] = cprev[m];
    __syncthreads();   // X staged + pbase staged

    for (int t = 0; t < 3; t++) {
#pragma unroll
        for (int k = 0; k < 4; k++) {
            int rr = lane + 32 * k;
            if (rr < NUMR) {
                const ulonglong2* xr = (const ulonglong2*)&sm[OFF_X4] + (t * NUMR + rr) * 9;
                ulonglong2 X0 = xr[0], X1 = xr[1], X2 = xr[2], X3 = xr[3];
                ulonglong2 X4 = xr[4], X5 = xr[5], X6 = xr[6], X7 = xr[7];
#pragma unroll
                for (int m = 0; m < 3; m++) {
                    int d = mb + m;
                    const ulonglong2* pp = (const ulonglong2*)&sm[pbase] + d * 8;
                    ull s0 = 0, s1 = 0;
                    ulonglong2 P;
                    P = pp[0]; fma2(s0, X0.x, P.x); fma2(s1, X0.y, P.y);
                    P = pp[1]; fma2(s0, X1.x, P.x); fma2(s1, X1.y, P.y);
                    P = pp[2]; fma2(s0, X2.x, P.x); fma2(s1, X2.y, P.y);
                    P = pp[3]; fma2(s0, X3.x, P.x); fma2(s1, X3.y, P.y);
                    P = pp[4]; fma2(s0, X4.x, P.x); fma2(s1, X4.y, P.y);
                    P = pp[5]; fma2(s0, X5.x, P.x); fma2(s1, X5.y, P.y);
                    P = pp[6]; fma2(s0, X6.x, P.x); fma2(s1, X6.y, P.y);
                    P = pp[7]; fma2(s0, X7.x, P.x); fma2(s1, X7.y, P.y);
                    sm[yb + t * 600 + d * NUMR + rr] = hadd2x2(s0, s1);
                }
            }
        }
    }
    __syncwarp();

    float fp_sum = 0.f, rp_sum = 0.f;

    // phase-B staging indices (6 float2 per thread per 32-k tile)
    int bj[6], bp[6];
#pragma unroll
    for (int r = 0; r < 6; r++) {
        int e = tid + r * NTHREADS;   // 0..3071
        bj[r] = e >> 4;               // row j 0..191
        bp[r] = e & 15;               // float2 pair within 32 k's
    }

    for (int it = 0; it < MAXIT; it++) {
        // ======== phase A: rhs = lv+la+lp+cin + sum_t u_t @ X_t  (own dofs) ========
        ull accp[3] = {0ull, 0ull, 0ull};
        for (int t = 0; t < 3; t++) {
            float V = Vb[t];
#pragma unroll
            for (int i = lane; i < 300; i += 32) {
                int gi = h * 300 + i;
                float y = sm[yb + t * 600 + gi];
                sm[wb + gi] = fminf(V, y) - fminf(V, -y);
            }
            __syncwarp();
            const ulonglong2* XT = (const ulonglong2*)&sm[OFF_XT4] + t * 25 * 32;
            const ulonglong2* W4 = (const ulonglong2*)&sm[wb];
#pragma unroll
            for (int rbk = 0; rbk < 25; rbk++) {
                ulonglong2 xt = XT[rbk * 32 + lane];
#pragma unroll
                for (int m = 0; m < 3; m++) {
                    ulonglong2 u4 = W4[(mb + m) * 25 + rbk];
                    fma2(accp[m], xt.x, u4.x);
                    fma2(accp[m], xt.y, u4.y);
                }
            }
            __syncwarp();
        }
#pragma unroll
        for (int m = 0; m < 3; m++)
            sm[rbase + (mb + m) * 32 + lane] =
                l[0][m] + l[1][m] + l[2][m] + cin[m] + hadd2(accp[m]);

        // ======== phase B: primal = Q_inv[:192,:192] @ rhs + pb ========
        ull acc2[3] = {0ull, 0ull, 0ull};

        // prefetch tile kc=0
        float2 pf[6];
#pragma unroll
        for (int r = 0; r < 6; r++)
            pf[r] = *(const float2*)(Qi + bj[r] * NHDIM + 2 * bp[r]);

        for (int kc = 0; kc < 6; kc++) {
#pragma unroll
            for (int r = 0; r < 6; r++)
                *(float2*)&sm[OFF_Q + bj[r] * 36 + 2 * bp[r]] = pf[r];
            if (kc < 5) {
#pragma unroll
                for (int r = 0; r < 6; r++)
                    pf[r] = *(const float2*)(Qi + bj[r] * NHDIM + (kc + 1) * 32 + 2 * bp[r]);
            }
            __syncthreads();   // tile ready (also covers rhs on kc=0)
            const ulonglong2* Qt  = (const ulonglong2*)&sm[OFF_Q];
            const ulonglong2* RVp = (const ulonglong2*)&sm[rbase - samp * 200 + OFF_RHS - OFF_RHS + bs * 200 + kc * 32 + OFF_RHS - OFF_RHS];
            RVp = (const ulonglong2*)&sm[OFF_RHS + bs * 200 + kc * 32];
#pragma unroll
            for (int g = 0; g < 8; g++) {
                ulonglong2 rv = RVp[g];
#pragma unroll
                for (int jg = 0; jg < 3; jg++) {
                    ulonglong2 q = Qt[(bj0 + jg * 4) * 9 + g];
                    fma2(acc2[jg], q.x, rv.x);
                    fma2(acc2[jg], q.y, rv.y);
                }
            }
            __syncthreads();   // all consumed before overwrite
        }
#pragma unroll
        for (int jg = 0; jg < 3; jg++)
            sm[OFF_PRIM + bs * 200 + bj0 + jg * 4] = hadd2(acc2[jg]) + pbq[jg];
        __syncthreads();       // full primal ready

        // ======== phase C: y update, residuals, lambda updates (own dofs) ========
        float dc = 0.f;
#pragma unroll
        for (int m = 0; m < 3; m++) {
            float pr = sm[pbase + (mb + m) * 32 + lane];
            float dd = pr - cprev[m];
            dc += dd * dd;
            cprev[m] = pr;
        }

        float resn[3], dsn[3], dln[3];
        for (int t = 0; t < 3; t++) {
            float V = Vb[t];
            float ra = 0.f, da = 0.f;
#pragma unroll
            for (int k = 0; k < 4; k++) {
                int rr = lane + 32 * k;
                if (rr < NUMR) {
                    const ulonglong2* xr = (const ulonglong2*)&sm[OFF_X4] + (t * NUMR + rr) * 9;
                    ulonglong2 X0 = xr[0], X1 = xr[1], X2 = xr[2], X3 = xr[3];
                    ulonglong2 X4 = xr[4], X5 = xr[5], X6 = xr[6], X7 = xr[7];
#pragma unroll
                    for (int m = 0; m < 3; m++) {
                        int d = mb + m;
                        const ulonglong2* pp = (const ulonglong2*)&sm[pbase] + d * 8;
                        ull s0 = 0, s1 = 0;
                        ulonglong2 P;
                        P = pp[0]; fma2(s0, X0.x, P.x); fma2(s1, X0.y, P.y);
                        P = pp[1]; fma2(s0, X1.x, P.x); fma2(s1, X1.y, P.y);
                        P = pp[2]; fma2(s0, X2.x, P.x); fma2(s1, X2.y, P.y);
                        P = pp[3]; fma2(s0, X3.x, P.x); fma2(s1, X3.y, P.y);
                        P = pp[4]; fma2(s0, X4.x, P.x); fma2(s1, X4.y, P.y);
                        P = pp[5]; fma2(s0, X5.x, P.x); fma2(s1, X5.y, P.y);
                        P = pp[6]; fma2(s0, X6.x, P.x); fma2(s1, X6.y, P.y);
                        P = pp[7]; fma2(s0, X7.x, P.x); fma2(s1, X7.y, P.y);
                        float yn = hadd2x2(s0, s1);
                        int i = t * 600 + d * NUMR + rr;
                        float yo = sm[yb + i];
                        float rt  = fmaxf(yn - V, 0.f);
                        float rbm = fmaxf(-yn - V, 0.f);
                        ra += rt * rt + rbm * rbm;
                        float d1 = fmaxf(V - yn, 0.f) - fmaxf(V - yo, 0.f);
                        float d2 = fmaxf(V + yn, 0.f) - fmaxf(V + yo, 0.f);
                        da += d1 * d1 + d2 * d2;
                        sm[yb + i] = yn;
                        sm[wb + d * NUMR + rr] = rt - rbm;
                    }
                }
            }
            resn[t] = ra;
            dsn[t]  = da;
            __syncwarp();
            // lambda update: dl = w @ X (own dofs)
            ull dlp[3] = {0ull, 0ull, 0ull};
            const ulonglong2* XT = (const ulonglong2*)&sm[OFF_XT4] + t * 25 * 32;
            const ulonglong2* W4 = (const ulonglong2*)&sm[wb];
#pragma unroll
            for (int rbk = 0; rbk < 25; rbk++) {
                ulonglong2 xt = XT[rbk * 32 + lane];
#pragma unroll
                for (int m = 0; m < 3; m++) {
                    ulonglong2 w4 = W4[(mb + m) * 25 + rbk];
                    fma2(dlp[m], xt.x, w4.x);
                    fma2(dlp[m], xt.y, w4.y);
                }
            }
            float dls = 0.f;
#pragma unroll
            for (int m = 0; m < 3; m++) {
                float dl = hadd2(dlp[m]);
                l[t][m] -= dl;
                dls += dl * dl;
            }
            dln[t] = dls;
            __syncwarp();
        }

        // intra-warp reduce of 10 partial squared norms
        float red[10] = {resn[0], resn[1], resn[2],
                         dsn[0],  dsn[1],  dsn[2],
                         dln[0],  dln[1],  dln[2], dc};
#pragma unroll
        for (int off = 16; off; off >>= 1)
#pragma unroll
            for (int q = 0; q < 10; q++)
                red[q] += __shfl_xor_sync(0xffffffffu, red[q], off);

        if (lane == 0) {
#pragma unroll
            for (int q = 0; q < 10; q++)
                sm[OFF_RED + warp * 12 + q] = red[q];
        }
        __syncthreads();
        {
            int wp = warp ^ 1;
            float tot[10];
#pragma unroll
            for (int q = 0; q < 10; q++)
                tot[q] = sm[OFF_RED + warp * 12 + q] + sm[OFF_RED + wp * 12 + q];
            rp_sum += sqrtf(tot[0]) + sqrtf(tot[1]) + sqrtf(tot[2]);
            fp_sum += sqrtf(tot[3]) + sqrtf(tot[4]) + sqrtf(tot[5])
                    + sqrtf(tot[6]) + sqrtf(tot[7]) + sqrtf(tot[8]) + sqrtf(tot[9]);
        }
        __syncthreads();
    }

    // ---- outputs ----
#pragma unroll
    for (int m = 0; m < 3; m++)
        out[s * NVAR + (mb + m) * 32 + lane] = cprev[m];
    if (h == 0 && lane == 0) {
        out[BATCH * NVAR + s]         = fp_sum * (1.0f / MAXIT);
        out[BATCH * NVAR + BATCH + s] = rp_sum * (1.0f / MAXIT);
    }
}

extern "C" void kernel_launch(void* const* d_in, const int* in_sizes, int n_in,
                              void* d_out, int out_size)
{
    const float* lamda = (const float*)d_in[0];
    const float* c_in  = (const float*)d_in[1];
    const float* c_s   = (const float*)d_in[2];
    const float* b_eq  = (const float*)d_in[3];
    const float* Av    = (const float*)d_in[4];
    const float* Aa    = (const float*)d_in[5];
    const float* Ap    = (const float*)d_in[6];
    const float* Qi    = (const float*)d_in[7];
    float* out = (float*)d_out;

    int smem_bytes = SMEM_FLOATS * sizeof(float);
    cudaFuncSetAttribute(proj_filter_kernel,
                         cudaFuncAttributeMaxDynamicSharedMemorySize, smem_bytes);
    proj_filter_kernel<<<BATCH / SPB, NTHREADS, smem_bytes>>>(
        lamda, c_in, c_s, b_eq, Av, Aa, Ap, Qi, out);
}

// round 4
// speedup vs baseline: 1.2861x; 1.1839x over previous
#include <cuda_runtime.h>
#include <math.h>

#define NUMR    100
#define BATCH   2048
#define NVAR    192
#define NEQC    30
#define NHDIM   222
#define MAXIT   15
#define SPB     8
#define NTHREADS 512

// shared memory float offsets
#define OFF_XT4  0        // 3*25*32 float4 = 9600 (X transposed, r-chunked)
#define OFF_X4   9600     // 3*100*36 = 10800 (X row-major, 36-float row stride)
#define OFF_Y    20400    // SPB * 1800 = 14400
#define OFF_W    34800    // SPB * 600 = 4800
#define OFF_RHS  39600    // SPB * 200 = 1600
#define OFF_PRIM 41200    // SPB * 200 = 1600
#define OFF_Q    42800    // 192 * 36 = 6912 (32-k tile)
#define OFF_RED  49712    // 16 warps * 12
#define OFF_G    49904    // 32*32 = 1024  (G = sum_t X_t^T X_t)
#define SMEM_FLOATS 50928 // 203,712 bytes

typedef unsigned long long ull;

__device__ __forceinline__ void fma2(ull& d, ull a, ull b) {
    asm("fma.rn.f32x2 %0, %1, %2, %0;" : "+l"(d) : "l"(a), "l"(b));
}
__device__ __forceinline__ float hadd2(ull v) {
    float lo, hi;
    asm("mov.b64 {%0, %1}, %2;" : "=f"(lo), "=f"(hi) : "l"(v));
    return lo + hi;
}
__device__ __forceinline__ float hadd2x2(ull a, ull b) {
    return hadd2(a) + hadd2(b);
}

__global__ void __launch_bounds__(NTHREADS, 1)
proj_filter_kernel(const float* __restrict__ lamda,
                   const float* __restrict__ c_in_g,
                   const float* __restrict__ c_samp,
                   const float* __restrict__ b_eq,
                   const float* __restrict__ Av,
                   const float* __restrict__ Aa,
                   const float* __restrict__ Ap,
                   const float* __restrict__ Qi,
                   float* __restrict__ out)
{
    extern __shared__ float sm[];
    const int tid   = threadIdx.x;
    const int warp  = tid >> 5;
    const int lane  = tid & 31;
    const int samp  = warp >> 1;
    const int h     = warp & 1;
    const int mb    = 3 * h;
    const int s     = blockIdx.x * SPB + samp;

    // phase-B role: lane = (br, bs)
    const int bs  = lane & 7;
    const int br  = lane >> 3;
    const int bj0 = warp * 12 + br;

    // ---- stage X matrices ----
    for (int idx = tid; idx < 3 * NUMR * 32; idx += NTHREADS) {
        int t   = idx / (NUMR * 32);
        int rem = idx - t * (NUMR * 32);
        int r = rem >> 5;
        int c = rem & 31;
        const float* Asrc = (t == 0) ? Av : ((t == 1) ? Aa : Ap);
        float v = Asrc[r * NVAR + c];
        sm[OFF_XT4 + ((t * 25 + (r >> 2)) * 32 + c) * 4 + (r & 3)] = v;
        sm[OFF_X4 + (t * NUMR + r) * 36 + c] = v;
    }
    __syncthreads();

    // ---- precompute G = sum_t X_t^T X_t (32x32) ----
    {
        int a = tid >> 5;      // 0..15 (warp-uniform)
        int b = tid & 31;
        float g0 = 0.f, g1 = 0.f;
        for (int g = 0; g < 300; g++) {
            float xb  = sm[OFF_X4 + g * 36 + b];
            float xa0 = sm[OFF_X4 + g * 36 + a];
            float xa1 = sm[OFF_X4 + g * 36 + a + 16];
            g0 += xa0 * xb;
            g1 += xa1 * xb;
        }
        sm[OFF_G + a * 32 + b]        = g0;
        sm[OFF_G + (a + 16) * 32 + b] = g1;
    }

    const float Vb[3] = {0.8f, 1.8f, 3.14159265358979323846f};

    const int yb    = OFF_Y    + samp * 1800;
    const int wb    = OFF_W    + samp * 600;
    const int rbase = OFF_RHS  + samp * 200;
    const int pbase = OFF_PRIM + samp * 200;

    // ---- per-sample per-half register state ----
    float cin[3], cprev[3], l[3][3], sdl[3];
#pragma unroll
    for (int m = 0; m < 3; m++) {
        int j = (mb + m) * 32 + lane;
        cin[m]   = c_in_g[s * NVAR + j];
        cprev[m] = c_samp[s * NVAR + j];
    }
#pragma unroll
    for (int t = 0; t < 3; t++)
#pragma unroll
        for (int m = 0; m < 3; m++)
            l[t][m] = lamda[s * (3 * NVAR) + t * NVAR + (mb + m) * 32 + lane];

    // pb (phase-B role, iteration-invariant)
    float pbq[3];
#pragma unroll
    for (int jg = 0; jg < 3; jg++) {
        int j = bj0 + jg * 4;
        float a = 0.f;
        const float* bq = b_eq + (blockIdx.x * SPB + bs) * NEQC;
        for (int k = 0; k < NEQC; k++)
            a += Qi[j * NHDIM + NVAR + k] * bq[k];
        pbq[jg] = a;
    }

    // ---- init: stage p0, compute y0 = X p0, w0, sdl0 = sum_t w0_t @ X_t ----
#pragma unroll
    for (int m = 0; m < 3; m++) sm[pbase + (mb + m) * 32 + lane] = cprev[m];
    __syncthreads();

#pragma unroll
    for (int m = 0; m < 3; m++) sdl[m] = 0.f;

    for (int t = 0; t < 3; t++) {
        float V = Vb[t];
#pragma unroll
        for (int k = 0; k < 4; k++) {
            int rr = lane + 32 * k;
            if (rr < NUMR) {
                const ulonglong2* xr = (const ulonglong2*)&sm[OFF_X4] + (t * NUMR + rr) * 9;
                ulonglong2 X0 = xr[0], X1 = xr[1], X2 = xr[2], X3 = xr[3];
                ulonglong2 X4 = xr[4], X5 = xr[5], X6 = xr[6], X7 = xr[7];
#pragma unroll
                for (int m = 0; m < 3; m++) {
                    int d = mb + m;
                    const ulonglong2* pp = (const ulonglong2*)&sm[pbase] + d * 8;
                    ull s0 = 0, s1 = 0;
                    ulonglong2 P;
                    P = pp[0]; fma2(s0, X0.x, P.x); fma2(s1, X0.y, P.y);
                    P = pp[1]; fma2(s0, X1.x, P.x); fma2(s1, X1.y, P.y);
                    P = pp[2]; fma2(s0, X2.x, P.x); fma2(s1, X2.y, P.y);
                    P = pp[3]; fma2(s0, X3.x, P.x); fma2(s1, X3.y, P.y);
                    P = pp[4]; fma2(s0, X4.x, P.x); fma2(s1, X4.y, P.y);
                    P = pp[5]; fma2(s0, X5.x, P.x); fma2(s1, X5.y, P.y);
                    P = pp[6]; fma2(s0, X6.x, P.x); fma2(s1, X6.y, P.y);
                    P = pp[7]; fma2(s0, X7.x, P.x); fma2(s1, X7.y, P.y);
                    float yn = hadd2x2(s0, s1);
                    sm[yb + t * 600 + d * NUMR + rr] = yn;
                    float rt  = fmaxf(yn - V, 0.f);
                    float rbm = fmaxf(-yn - V, 0.f);
                    sm[wb + d * NUMR + rr] = rt - rbm;
                }
            }
        }
        __syncwarp();
        // sdl += w0_t @ X_t
        ull dlp[3] = {0ull, 0ull, 0ull};
        const ulonglong2* XT = (const ulonglong2*)&sm[OFF_XT4] + t * 25 * 32;
        const ulonglong2* W4 = (const ulonglong2*)&sm[wb];
#pragma unroll
        for (int rbk = 0; rbk < 25; rbk++) {
            ulonglong2 xt = XT[rbk * 32 + lane];
#pragma unroll
            for (int m = 0; m < 3; m++) {
                ulonglong2 w4 = W4[(mb + m) * 25 + rbk];
                fma2(dlp[m], xt.x, w4.x);
                fma2(dlp[m], xt.y, w4.y);
            }
        }
#pragma unroll
        for (int m = 0; m < 3; m++) sdl[m] += hadd2(dlp[m]);
        __syncwarp();
    }
    __syncthreads();   // G ready (and init writes drained)

    float fp_sum = 0.f, rp_sum = 0.f;

    // phase-B staging indices (6 float2 per thread per 32-k tile)
    int bj[6], bp[6];
#pragma unroll
    for (int r = 0; r < 6; r++) {
        int e = tid + r * NTHREADS;
        bj[r] = e >> 4;
        bp[r] = e & 15;
    }

    for (int it = 0; it < MAXIT; it++) {
        // ======== phase A: gp = G @ p ; rhs = l + cin + 2 gp - sdl ========
        float gp0 = 0.f, gp1 = 0.f, gp2 = 0.f;
        const float* Gm = &sm[OFF_G];
        const float* P0 = &sm[pbase + (mb + 0) * 32];
        const float* P1 = &sm[pbase + (mb + 1) * 32];
        const float* P2 = &sm[pbase + (mb + 2) * 32];
#pragma unroll 8
        for (int k = 0; k < 32; k++) {
            float gk = Gm[k * 32 + lane];
            gp0 += gk * P0[k];
            gp1 += gk * P1[k];
            gp2 += gk * P2[k];
        }
        {
            float gpv[3] = {gp0, gp1, gp2};
#pragma unroll
            for (int m = 0; m < 3; m++)
                sm[rbase + (mb + m) * 32 + lane] =
                    l[0][m] + l[1][m] + l[2][m] + cin[m] + 2.f * gpv[m] - sdl[m];
        }

        // ======== phase B: primal = Q_inv[:192,:192] @ rhs + pb ========
        ull acc2[3] = {0ull, 0ull, 0ull};

        float2 pf[6];
#pragma unroll
        for (int r = 0; r < 6; r++)
            pf[r] = *(const float2*)(Qi + bj[r] * NHDIM + 2 * bp[r]);

        for (int kc = 0; kc < 6; kc++) {
#pragma unroll
            for (int r = 0; r < 6; r++)
                *(float2*)&sm[OFF_Q + bj[r] * 36 + 2 * bp[r]] = pf[r];
            if (kc < 5) {
#pragma unroll
                for (int r = 0; r < 6; r++)
                    pf[r] = *(const float2*)(Qi + bj[r] * NHDIM + (kc + 1) * 32 + 2 * bp[r]);
            }
            __syncthreads();   // tile ready (covers rhs on kc=0)
            const ulonglong2* Qt  = (const ulonglong2*)&sm[OFF_Q];
            const ulonglong2* RVp = (const ulonglong2*)&sm[OFF_RHS + bs * 200 + kc * 32];
#pragma unroll
            for (int g = 0; g < 8; g++) {
                ulonglong2 rv = RVp[g];
#pragma unroll
                for (int jg = 0; jg < 3; jg++) {
                    ulonglong2 q = Qt[(bj0 + jg * 4) * 9 + g];
                    fma2(acc2[jg], q.x, rv.x);
                    fma2(acc2[jg], q.y, rv.y);
                }
            }
            __syncthreads();
        }
#pragma unroll
        for (int jg = 0; jg < 3; jg++)
            sm[OFF_PRIM + bs * 200 + bj0 + jg * 4] = hadd2(acc2[jg]) + pbq[jg];
        __syncthreads();   // full primal ready

        // ======== phase C: y update, w, norms, lambda updates ========
        float dc = 0.f;
#pragma unroll
        for (int m = 0; m < 3; m++) {
            float pr = sm[pbase + (mb + m) * 32 + lane];
            float dd = pr - cprev[m];
            dc += dd * dd;
            cprev[m] = pr;
        }
#pragma unroll
        for (int m = 0; m < 3; m++) sdl[m] = 0.f;

        float resn[3], dsn[3], dln[3];
        for (int t = 0; t < 3; t++) {
            float V = Vb[t];
            float ra = 0.f, da = 0.f;
#pragma unroll
            for (int k = 0; k < 4; k++) {
                int rr = lane + 32 * k;
                if (rr < NUMR) {
                    const ulonglong2* xr = (const ulonglong2*)&sm[OFF_X4] + (t * NUMR + rr) * 9;
                    ulonglong2 X0 = xr[0], X1 = xr[1], X2 = xr[2], X3 = xr[3];
                    ulonglong2 X4 = xr[4], X5 = xr[5], X6 = xr[6], X7 = xr[7];
#pragma unroll
                    for (int m = 0; m < 3; m++) {
                        int d = mb + m;
                        const ulonglong2* pp = (const ulonglong2*)&sm[pbase] + d * 8;
                        ull s0 = 0, s1 = 0;
                        ulonglong2 P;
                        P = pp[0]; fma2(s0, X0.x, P.x); fma2(s1, X0.y, P.y);
                        P = pp[1]; fma2(s0, X1.x, P.x); fma2(s1, X1.y, P.y);
                        P = pp[2]; fma2(s0, X2.x, P.x); fma2(s1, X2.y, P.y);
                        P = pp[3]; fma2(s0, X3.x, P.x); fma2(s1, X3.y, P.y);
                        P = pp[4]; fma2(s0, X4.x, P.x); fma2(s1, X4.y, P.y);
                        P = pp[5]; fma2(s0, X5.x, P.x); fma2(s1, X5.y, P.y);
                        P = pp[6]; fma2(s0, X6.x, P.x); fma2(s1, X6.y, P.y);
                        P = pp[7]; fma2(s0, X7.x, P.x); fma2(s1, X7.y, P.y);
                        float yn = hadd2x2(s0, s1);
                        int i = t * 600 + d * NUMR + rr;
                        float yo = sm[yb + i];
                        float rt  = fmaxf(yn - V, 0.f);
                        float rbm = fmaxf(-yn - V, 0.f);
                        ra += rt * rt + rbm * rbm;
                        float d1 = fmaxf(V - yn, 0.f) - fmaxf(V - yo, 0.f);
                        float d2 = fmaxf(V + yn, 0.f) - fmaxf(V + yo, 0.f);
                        da += d1 * d1 + d2 * d2;
                        sm[yb + i] = yn;
                        sm[wb + d * NUMR + rr] = rt - rbm;
                    }
                }
            }
            resn[t] = ra;
            dsn[t]  = da;
            __syncwarp();
            // lambda update: dl = w @ X
            ull dlp[3] = {0ull, 0ull, 0ull};
            const ulonglong2* XT = (const ulonglong2*)&sm[OFF_XT4] + t * 25 * 32;
            const ulonglong2* W4 = (const ulonglong2*)&sm[wb];
#pragma unroll
            for (int rbk = 0; rbk < 25; rbk++) {
                ulonglong2 xt = XT[rbk * 32 + lane];
#pragma unroll
                for (int m = 0; m < 3; m++) {
                    ulonglong2 w4 = W4[(mb + m) * 25 + rbk];
                    fma2(dlp[m], xt.x, w4.x);
                    fma2(dlp[m], xt.y, w4.y);
                }
            }
            float dls = 0.f;
#pragma unroll
            for (int m = 0; m < 3; m++) {
                float dl = hadd2(dlp[m]);
                l[t][m] -= dl;
                sdl[m]  += dl;
                dls += dl * dl;
            }
            dln[t] = dls;
            __syncwarp();
        }

        // intra-warp reduce of 10 partial squared norms
        float red[10] = {resn[0], resn[1], resn[2],
                         dsn[0],  dsn[1],  dsn[2],
                         dln[0],  dln[1],  dln[2], dc};
#pragma unroll
        for (int off = 16; off; off >>= 1)
#pragma unroll
            for (int q = 0; q < 10; q++)
                red[q] += __shfl_xor_sync(0xffffffffu, red[q], off);

        if (lane == 0) {
#pragma unroll
            for (int q = 0; q < 10; q++)
                sm[OFF_RED + warp * 12 + q] = red[q];
        }
        __syncthreads();
        {
            int wp = warp ^ 1;
            float tot[10];
#pragma unroll
            for (int q = 0; q < 10; q++)
                tot[q] = sm[OFF_RED + warp * 12 + q] + sm[OFF_RED + wp * 12 + q];
            rp_sum += sqrtf(tot[0]) + sqrtf(tot[1]) + sqrtf(tot[2]);
            fp_sum += sqrtf(tot[3]) + sqrtf(tot[4]) + sqrtf(tot[5])
                    + sqrtf(tot[6]) + sqrtf(tot[7]) + sqrtf(tot[8]) + sqrtf(tot[9]);
        }
        __syncthreads();
    }

    // ---- outputs ----
#pragma unroll
    for (int m = 0; m < 3; m++)
        out[s * NVAR + (mb + m) * 32 + lane] = cprev[m];
    if (h == 0 && lane == 0) {
        out[BATCH * NVAR + s]         = fp_sum * (1.0f / MAXIT);
        out[BATCH * NVAR + BATCH + s] = rp_sum * (1.0f / MAXIT);
    }
}

extern "C" void kernel_launch(void* const* d_in, const int* in_sizes, int n_in,
                              void* d_out, int out_size)
{
    const float* lamda = (const float*)d_in[0];
    const float* c_in  = (const float*)d_in[1];
    const float* c_s   = (const float*)d_in[2];
    const float* b_eq  = (const float*)d_in[3];
    const float* Av    = (const float*)d_in[4];
    const float* Aa    = (const float*)d_in[5];
    const float* Ap    = (const float*)d_in[6];
    const float* Qi    = (const float*)d_in[7];
    float* out = (float*)d_out;

    int smem_bytes = SMEM_FLOATS * sizeof(float);
    cudaFuncSetAttribute(proj_filter_kernel,
                         cudaFuncAttributeMaxDynamicSharedMemorySize, smem_bytes);
    proj_filter_kernel<<<BATCH / SPB, NTHREADS, smem_bytes>>>(
        lamda, c_in, c_s, b_eq, Av, Aa, Ap, Qi, out);
}

// round 5
// speedup vs baseline: 1.3888x; 1.0798x over previous
#include <cuda_runtime.h>
#include <math.h>

#define NUMR    100
#define BATCH   2048
#define NVAR    192
#define NEQC    30
#define NHDIM   222
#define MAXIT   15
#define SPB     8
#define NTHREADS 512

// shared memory float offsets
#define OFF_X4   0        // 300*32 = 9600 (X rows, stride 32)
#define OFF_Y    9600     // 3*100*48 = 14400  ([t][r][col48])
#define OFF_W    24000    // 14400
#define OFF_P    38400    // 48*36 = 1728  ([col][k], stride 36)
#define OFF_RHS  40128    // 8*196 = 1568
#define OFF_Q    41696    // 192*20 = 3840 (16-k tile)
#define OFF_DL   45536    // 96*49 = 4704  ([t*32+k][col], stride 49)
#define OFF_PART 50240    // 6*16*49 = 4704 ([kind*3+t][warp][col], stride 49)
#define OFF_G    54944    // 32*32 = 1024
#define OFF_RED  55968    // 16*12 = 192
#define SMEM_FLOATS 56160 // 224,640 bytes

typedef unsigned long long ull;

__device__ __forceinline__ void fma2(ull& d, ull a, ull b) {
    asm("fma.rn.f32x2 %0, %1, %2, %0;" : "+l"(d) : "l"(a), "l"(b));
}
__device__ __forceinline__ float hadd2(ull v) {
    float lo, hi;
    asm("mov.b64 {%0, %1}, %2;" : "=f"(lo), "=f"(hi) : "l"(v));
    return lo + hi;
}
__device__ __forceinline__ ull pack2(float v) {
    ull r; asm("mov.b64 %0, {%1, %1};" : "=l"(r) : "f"(v)); return r;
}
__device__ __forceinline__ void unpack2(float& lo, float& hi, ull v) {
    asm("mov.b64 {%0, %1}, %2;" : "=f"(lo), "=f"(hi) : "l"(v));
}

__global__ void __launch_bounds__(NTHREADS, 1)
proj_filter_kernel(const float* __restrict__ lamda,
                   const float* __restrict__ c_in_g,
                   const float* __restrict__ c_samp,
                   const float* __restrict__ b_eq,
                   const float* __restrict__ Av,
                   const float* __restrict__ Aa,
                   const float* __restrict__ Ap,
                   const float* __restrict__ Qi,
                   float* __restrict__ out)
{
    extern __shared__ float sm[];
    const int tid   = threadIdx.x;
    const int warp  = tid >> 5;
    const int lane  = tid & 31;
    const int samp  = warp >> 1;
    const int h     = warp & 1;
    const int mb    = 3 * h;
    const int s     = blockIdx.x * SPB + samp;
    const int col0  = samp * 6 + mb;       // first owned column

    // phase-B role
    const int bs  = lane & 7;
    const int br  = lane >> 3;
    const int bj0 = warp * 12 + br;

    const float Vb[3] = {0.8f, 1.8f, 3.14159265358979323846f};

    // ---- stage X (300 rows x 32) ----
    for (int idx = tid; idx < 300 * 32; idx += NTHREADS) {
        int t   = idx / 3200;
        int rem = idx - t * 3200;
        int r = rem >> 5;
        int c = rem & 31;
        const float* Asrc = (t == 0) ? Av : ((t == 1) ? Aa : Ap);
        sm[OFF_X4 + (t * NUMR + r) * 32 + c] = Asrc[r * NVAR + c];
    }
    __syncthreads();

    // ---- G = sum_t X_t^T X_t ----
    {
        int a = warp;            // 0..15
        int b = lane;
        float g0 = 0.f, g1 = 0.f;
        for (int g = 0; g < 300; g++) {
            float xb  = sm[OFF_X4 + g * 32 + b];
            g0 += sm[OFF_X4 + g * 32 + a] * xb;
            g1 += sm[OFF_X4 + g * 32 + a + 16] * xb;
        }
        sm[OFF_G + a * 32 + b]        = g0;
        sm[OFF_G + (a + 16) * 32 + b] = g1;
    }

    // ---- per-sample state ----
    float cin[3], cprev[3], l[3][3], sdl[3];
#pragma unroll
    for (int m = 0; m < 3; m++) {
        int j = (mb + m) * 32 + lane;
        cin[m]   = c_in_g[s * NVAR + j];
        cprev[m] = c_samp[s * NVAR + j];
    }
#pragma unroll
    for (int t = 0; t < 3; t++)
#pragma unroll
        for (int m = 0; m < 3; m++)
            l[t][m] = lamda[s * (3 * NVAR) + t * NVAR + (mb + m) * 32 + lane];

    float pbq[3];
#pragma unroll
    for (int jg = 0; jg < 3; jg++) {
        int j = bj0 + jg * 4;
        float a = 0.f;
        const float* bq = b_eq + (blockIdx.x * SPB + bs) * NEQC;
        for (int k = 0; k < NEQC; k++)
            a += Qi[j * NHDIM + NVAR + k] * bq[k];
        pbq[jg] = a;
    }

    // stage initial P (p0 = c_samp)
#pragma unroll
    for (int m = 0; m < 3; m++)
        sm[OFF_P + (col0 + m) * 36 + lane] = cprev[m];
    __syncthreads();   // X, G, P ready

    // ---- D0: row-parallel y0/w0 (no old-y, no norms) ----
    {
        ull PA[16], PB[16];
        const ulonglong2* PcA = (const ulonglong2*)&sm[OFF_P + lane * 36];
        const ulonglong2* PcB = (const ulonglong2*)&sm[OFF_P + (32 + (lane & 15)) * 36];
#pragma unroll
        for (int q = 0; q < 8; q++) {
            ulonglong2 a = PcA[q]; PA[2*q] = a.x; PA[2*q+1] = a.y;
            ulonglong2 b = PcB[q]; PB[2*q] = b.x; PB[2*q+1] = b.y;
        }
#pragma unroll
        for (int t = 0; t < 3; t++) {
            float V = Vb[t];
#pragma unroll
            for (int i = 0; i < 7; i++) {
                int r = warp + 16 * i;
                if (r < NUMR) {
                    const ulonglong2* Xr = (const ulonglong2*)&sm[OFF_X4 + (t * NUMR + r) * 32];
                    ull aA = 0, aB = 0;
#pragma unroll
                    for (int q = 0; q < 8; q++) {
                        ulonglong2 x = Xr[q];
                        fma2(aA, x.x, PA[2*q]); fma2(aA, x.y, PA[2*q+1]);
                        fma2(aB, x.x, PB[2*q]); fma2(aB, x.y, PB[2*q+1]);
                    }
                    float ynA = hadd2(aA), ynB = hadd2(aB);
                    int base = t * 4800 + r * 48;
                    sm[OFF_Y + base + lane] = ynA;
                    sm[OFF_W + base + lane] = fmaxf(ynA - V, 0.f) - fmaxf(-ynA - V, 0.f);
                    if (lane < 16) {
                        sm[OFF_Y + base + 32 + lane] = ynB;
                        sm[OFF_W + base + 32 + lane] = fmaxf(ynB - V, 0.f) - fmaxf(-ynB - V, 0.f);
                    }
                }
            }
        }
    }
    __syncthreads();

    // ---- E0: dl0 ----
    if (warp < 12) {
        int t  = warp >> 2;
        int k0 = (warp & 3) * 8;
        ull dA[4] = {0,0,0,0}, dB[4] = {0,0,0,0};
        for (int r = 0; r < NUMR; r++) {
            const ulonglong2* Xr = (const ulonglong2*)&sm[OFF_X4 + (t * NUMR + r) * 32 + k0];
            int wbase = OFF_W + t * 4800 + r * 48;
            ull wpA = pack2(sm[wbase + lane]);
            ull wpB = pack2(sm[wbase + 32 + (lane & 15)]);
            ulonglong2 x0 = Xr[0], x1 = Xr[1];
            fma2(dA[0], x0.x, wpA); fma2(dA[1], x0.y, wpA);
            fma2(dA[2], x1.x, wpA); fma2(dA[3], x1.y, wpA);
            fma2(dB[0], x0.x, wpB); fma2(dB[1], x0.y, wpB);
            fma2(dB[2], x1.x, wpB); fma2(dB[3], x1.y, wpB);
        }
#pragma unroll
        for (int j = 0; j < 4; j++) {
            float lo, hi;
            unpack2(lo, hi, dA[j]);
            sm[OFF_DL + (t * 32 + k0 + 2*j    ) * 49 + lane] = lo;
            sm[OFF_DL + (t * 32 + k0 + 2*j + 1) * 49 + lane] = hi;
            if (lane < 16) {
                unpack2(lo, hi, dB[j]);
                sm[OFF_DL + (t * 32 + k0 + 2*j    ) * 49 + 32 + lane] = lo;
                sm[OFF_DL + (t * 32 + k0 + 2*j + 1) * 49 + 32 + lane] = hi;
            }
        }
    }
    __syncthreads();

    // ---- F0-lite: sdl0 ----
#pragma unroll
    for (int m = 0; m < 3; m++) sdl[m] = 0.f;
#pragma unroll
    for (int t = 0; t < 3; t++)
#pragma unroll
        for (int m = 0; m < 3; m++)
            sdl[m] += sm[OFF_DL + (t * 32 + lane) * 49 + col0 + m];

    float fp_sum = 0.f, rp_sum = 0.f;

    // phase-B staging indices (3 float2 per thread per 16-k tile)
    int bj[3], bp[3];
#pragma unroll
    for (int r = 0; r < 3; r++) {
        int e = tid + r * NTHREADS;   // 0..1535
        bj[r] = e >> 3;
        bp[r] = e & 7;
    }

    for (int it = 0; it < MAXIT; it++) {
        // ======== A: gp = G@p ; rhs ========
        {
            const float* Gm = &sm[OFF_G];
            const float* P0 = &sm[OFF_P + col0 * 36];
            const float* P1 = P0 + 36;
            const float* P2 = P0 + 72;
            float g0 = 0.f, g1 = 0.f, g2 = 0.f;
#pragma unroll 8
            for (int k = 0; k < 32; k++) {
                float gk = Gm[k * 32 + lane];
                g0 += gk * P0[k]; g1 += gk * P1[k]; g2 += gk * P2[k];
            }
            float gpv[3] = {g0, g1, g2};
#pragma unroll
            for (int m = 0; m < 3; m++)
                sm[OFF_RHS + samp * 196 + (mb + m) * 32 + lane] =
                    l[0][m] + l[1][m] + l[2][m] + cin[m] + 2.f * gpv[m] - sdl[m];
        }

        // ======== B: primal = Qinv @ rhs + pb ========
        ull acc2[3] = {0ull, 0ull, 0ull};
        float2 pf[3];
#pragma unroll
        for (int r = 0; r < 3; r++)
            pf[r] = *(const float2*)(Qi + bj[r] * NHDIM + 2 * bp[r]);

        for (int kc = 0; kc < 12; kc++) {
#pragma unroll
            for (int r = 0; r < 3; r++)
                *(float2*)&sm[OFF_Q + bj[r] * 20 + 2 * bp[r]] = pf[r];
            if (kc < 11) {
#pragma unroll
                for (int r = 0; r < 3; r++)
                    pf[r] = *(const float2*)(Qi + bj[r] * NHDIM + (kc + 1) * 16 + 2 * bp[r]);
            }
            __syncthreads();
            const ulonglong2* Qt  = (const ulonglong2*)&sm[OFF_Q];
            const ulonglong2* RVp = (const ulonglong2*)&sm[OFF_RHS + bs * 196 + kc * 16];
#pragma unroll
            for (int g = 0; g < 4; g++) {
                ulonglong2 rv = RVp[g];
#pragma unroll
                for (int jg = 0; jg < 3; jg++) {
                    ulonglong2 q = Qt[(bj0 + jg * 4) * 5 + g];
                    fma2(acc2[jg], q.x, rv.x);
                    fma2(acc2[jg], q.y, rv.y);
                }
            }
            __syncthreads();
        }
#pragma unroll
        for (int jg = 0; jg < 3; jg++) {
            int j = bj0 + jg * 4;
            sm[OFF_P + (bs * 6 + (j >> 5)) * 36 + (j & 31)] = hadd2(acc2[jg]) + pbq[jg];
        }
        __syncthreads();   // P_new ready

        // ======== C: dc ========
        float dc = 0.f;
#pragma unroll
        for (int m = 0; m < 3; m++) {
            float pr = sm[OFF_P + (col0 + m) * 36 + lane];
            float dd = pr - cprev[m];
            dc += dd * dd;
            cprev[m] = pr;
        }

        // ======== D: row-parallel y/w + res/ds partials ========
        {
            ull PA[16], PB[16];
            const ulonglong2* PcA = (const ulonglong2*)&sm[OFF_P + lane * 36];
            const ulonglong2* PcB = (const ulonglong2*)&sm[OFF_P + (32 + (lane & 15)) * 36];
#pragma unroll
            for (int q = 0; q < 8; q++) {
                ulonglong2 a = PcA[q]; PA[2*q] = a.x; PA[2*q+1] = a.y;
                ulonglong2 b = PcB[q]; PB[2*q] = b.x; PB[2*q+1] = b.y;
            }
#pragma unroll
            for (int t = 0; t < 3; t++) {
                float V = Vb[t];
                float raA = 0.f, daA = 0.f, raB = 0.f, daB = 0.f;
#pragma unroll
                for (int i = 0; i < 7; i++) {
                    int r = warp + 16 * i;
                    if (r < NUMR) {
                        const ulonglong2* Xr = (const ulonglong2*)&sm[OFF_X4 + (t * NUMR + r) * 32];
                        ull aA = 0, aB = 0;
#pragma unroll
                        for (int q = 0; q < 8; q++) {
                            ulonglong2 x = Xr[q];
                            fma2(aA, x.x, PA[2*q]); fma2(aA, x.y, PA[2*q+1]);
                            fma2(aB, x.x, PB[2*q]); fma2(aB, x.y, PB[2*q+1]);
                        }
                        float ynA = hadd2(aA), ynB = hadd2(aB);
                        int base = t * 4800 + r * 48;
                        float yoA = sm[OFF_Y + base + lane];
                        float rtA = fmaxf(ynA - V, 0.f);
                        float rbA = fmaxf(-ynA - V, 0.f);
                        raA += rtA * rtA + rbA * rbA;
                        float d1 = fmaxf(V - ynA, 0.f) - fmaxf(V - yoA, 0.f);
                        float d2 = fmaxf(V + ynA, 0.f) - fmaxf(V + yoA, 0.f);
                        daA += d1 * d1 + d2 * d2;
                        sm[OFF_Y + base + lane] = ynA;
                        sm[OFF_W + base + lane] = rtA - rbA;
                        if (lane < 16) {
                            float yoB = sm[OFF_Y + base + 32 + lane];
                            float rtB = fmaxf(ynB - V, 0.f);
                            float rbB = fmaxf(-ynB - V, 0.f);
                            raB += rtB * rtB + rbB * rbB;
                            float e1 = fmaxf(V - ynB, 0.f) - fmaxf(V - yoB, 0.f);
                            float e2 = fmaxf(V + ynB, 0.f) - fmaxf(V + yoB, 0.f);
                            daB += e1 * e1 + e2 * e2;
                            sm[OFF_Y + base + 32 + lane] = ynB;
                            sm[OFF_W + base + 32 + lane] = rtB - rbB;
                        }
                    }
                }
                sm[OFF_PART + ((0 * 3 + t) * 16 + warp) * 49 + lane] = raA;
                sm[OFF_PART + ((1 * 3 + t) * 16 + warp) * 49 + lane] = daA;
                if (lane < 16) {
                    sm[OFF_PART + ((0 * 3 + t) * 16 + warp) * 49 + 32 + lane] = raB;
                    sm[OFF_PART + ((1 * 3 + t) * 16 + warp) * 49 + 32 + lane] = daB;
                }
            }
        }
        __syncthreads();

        // ======== E: dl = X^T w ========
        if (warp < 12) {
            int t  = warp >> 2;
            int k0 = (warp & 3) * 8;
            ull dA[4] = {0,0,0,0}, dB[4] = {0,0,0,0};
            for (int r = 0; r < NUMR; r++) {
                const ulonglong2* Xr = (const ulonglong2*)&sm[OFF_X4 + (t * NUMR + r) * 32 + k0];
                int wbase = OFF_W + t * 4800 + r * 48;
                ull wpA = pack2(sm[wbase + lane]);
                ull wpB = pack2(sm[wbase + 32 + (lane & 15)]);
                ulonglong2 x0 = Xr[0], x1 = Xr[1];
                fma2(dA[0], x0.x, wpA); fma2(dA[1], x0.y, wpA);
                fma2(dA[2], x1.x, wpA); fma2(dA[3], x1.y, wpA);
                fma2(dB[0], x0.x, wpB); fma2(dB[1], x0.y, wpB);
                fma2(dB[2], x1.x, wpB); fma2(dB[3], x1.y, wpB);
            }
#pragma unroll
            for (int j = 0; j < 4; j++) {
                float lo, hi;
                unpack2(lo, hi, dA[j]);
                sm[OFF_DL + (t * 32 + k0 + 2*j    ) * 49 + lane] = lo;
                sm[OFF_DL + (t * 32 + k0 + 2*j + 1) * 49 + lane] = hi;
                if (lane < 16) {
                    unpack2(lo, hi, dB[j]);
                    sm[OFF_DL + (t * 32 + k0 + 2*j    ) * 49 + 32 + lane] = lo;
                    sm[OFF_DL + (t * 32 + k0 + 2*j + 1) * 49 + 32 + lane] = hi;
                }
            }
        }
        __syncthreads();

        // ======== F: lambda update, sdl, norms ========
        float dln[3];
#pragma unroll
        for (int m = 0; m < 3; m++) sdl[m] = 0.f;
#pragma unroll
        for (int t = 0; t < 3; t++) {
            float dls = 0.f;
#pragma unroll
            for (int m = 0; m < 3; m++) {
                float dl = sm[OFF_DL + (t * 32 + lane) * 49 + col0 + m];
                l[t][m] -= dl;
                sdl[m]  += dl;
                dls += dl * dl;
            }
            dln[t] = dls;
        }
        float rds[6];
#pragma unroll
        for (int q = 0; q < 6; q++) {
            float v = 0.f;
            if (lane < 16) {
                int base = OFF_PART + (q * 16 + lane) * 49 + col0;
                v = sm[base] + sm[base + 1] + sm[base + 2];
            }
            rds[q] = v;
        }

        float red[10] = {rds[0], rds[1], rds[2],
                         rds[3], rds[4], rds[5],
                         dln[0], dln[1], dln[2], dc};
#pragma unroll
        for (int off = 16; off; off >>= 1)
#pragma unroll
            for (int q = 0; q < 10; q++)
                red[q] += __shfl_xor_sync(0xffffffffu, red[q], off);

        if (lane == 0) {
#pragma unroll
            for (int q = 0; q < 10; q++)
                sm[OFF_RED + warp * 12 + q] = red[q];
        }
        __syncthreads();
        {
            int wp = warp ^ 1;
            float tot[10];
#pragma unroll
            for (int q = 0; q < 10; q++)
                tot[q] = sm[OFF_RED + warp * 12 + q] + sm[OFF_RED + wp * 12 + q];
            rp_sum += sqrtf(tot[0]) + sqrtf(tot[1]) + sqrtf(tot[2]);
            fp_sum += sqrtf(tot[3]) + sqrtf(tot[4]) + sqrtf(tot[5])
                    + sqrtf(tot[6]) + sqrtf(tot[7]) + sqrtf(tot[8]) + sqrtf(tot[9]);
        }
        // no trailing sync needed: RED rewritten only after >=4 barriers next iter
    }

    // ---- outputs ----
#pragma unroll
    for (int m = 0; m < 3; m++)
        out[s * NVAR + (mb + m) * 32 + lane] = cprev[m];
    if (h == 0 && lane == 0) {
        out[BATCH * NVAR + s]         = fp_sum * (1.0f / MAXIT);
        out[BATCH * NVAR + BATCH + s] = rp_sum * (1.0f / MAXIT);
    }
}

extern "C" void kernel_launch(void* const* d_in, const int* in_sizes, int n_in,
                              void* d_out, int out_size)
{
    const float* lamda = (const float*)d_in[0];
    const float* c_in  = (const float*)d_in[1];
    const float* c_s   = (const float*)d_in[2];
    const float* b_eq  = (const float*)d_in[3];
    const float* Av    = (const float*)d_in[4];
    const float* Aa    = (const float*)d_in[5];
    const float* Ap    = (const float*)d_in[6];
    const float* Qi    = (const float*)d_in[7];
    float* out = (float*)d_out;

    int smem_bytes = SMEM_FLOATS * sizeof(float);
    cudaFuncSetAttribute(proj_filter_kernel,
                         cudaFuncAttributeMaxDynamicSharedMemorySize, smem_bytes);
    proj_filter_kernel<<<BATCH / SPB, NTHREADS, smem_bytes>>>(
        lamda, c_in, c_s, b_eq, Av, Aa, Ap, Qi, out);
}

// round 6
// speedup vs baseline: 1.5895x; 1.1445x over previous
#include <cuda_runtime.h>
#include <math.h>

#define NUMR    100
#define BATCH   2048
#define NVAR    192
#define NEQC    30
#define NHDIM   222
#define MAXIT   15
#define SPB     8
#define NTHREADS 512

// shared memory float offsets
#define OFF_X4   0        // 300*32 = 9600 (X rows, stride 32)
#define OFF_Y    9600     // 3*100*48 = 14400  ([t][r][col48])
#define OFF_W    24000    // 14400
#define OFF_P    38400    // 48*36 = 1728  ([col][k], stride 36)
#define OFF_RHS  40128    // 8*196 = 1568
#define OFF_DL   41696    // 96*49 = 4704  ([t*32+k][col], stride 49)
#define OFF_PART 46400    // 6*16*49 = 4704
#define OFF_G    51104    // 32*32 = 1024
#define OFF_RED  52128    // 16*12 = 192
#define SMEM_FLOATS 52320 // 209,280 bytes

typedef unsigned long long ull;

// 16B-aligned padded copy of Q_inv[:192,:192] (row stride 192 floats)
__device__ __align__(16) float Qpad[NVAR * NVAR];

__device__ __forceinline__ void fma2(ull& d, ull a, ull b) {
    asm("fma.rn.f32x2 %0, %1, %2, %0;" : "+l"(d) : "l"(a), "l"(b));
}
__device__ __forceinline__ float hadd2(ull v) {
    float lo, hi;
    asm("mov.b64 {%0, %1}, %2;" : "=f"(lo), "=f"(hi) : "l"(v));
    return lo + hi;
}
__device__ __forceinline__ ull pack2(float v) {
    ull r; asm("mov.b64 %0, {%1, %1};" : "=l"(r) : "f"(v)); return r;
}
__device__ __forceinline__ void unpack2(float& lo, float& hi, ull v) {
    asm("mov.b64 {%0, %1}, %2;" : "=f"(lo), "=f"(hi) : "l"(v));
}

__global__ void qprep_kernel(const float* __restrict__ Qi)
{
    int idx = blockIdx.x * blockDim.x + threadIdx.x;
    if (idx < NVAR * NVAR) {
        int j = idx / NVAR;
        int k = idx - j * NVAR;
        Qpad[idx] = Qi[j * NHDIM + k];
    }
}

__global__ void __launch_bounds__(NTHREADS, 1)
proj_filter_kernel(const float* __restrict__ lamda,
                   const float* __restrict__ c_in_g,
                   const float* __restrict__ c_samp,
                   const float* __restrict__ b_eq,
                   const float* __restrict__ Av,
                   const float* __restrict__ Aa,
                   const float* __restrict__ Ap,
                   const float* __restrict__ Qi,
                   float* __restrict__ out)
{
    extern __shared__ float sm[];
    const int tid   = threadIdx.x;
    const int warp  = tid >> 5;
    const int lane  = tid & 31;
    const int samp  = warp >> 1;
    const int h     = warp & 1;
    const int mb    = 3 * h;
    const int s     = blockIdx.x * SPB + samp;
    const int col0  = samp * 6 + mb;

    // phase-B role
    const int bs  = lane & 7;
    const int br  = lane >> 3;
    const int bj0 = warp * 12 + br;

    const float Vb[3] = {0.8f, 1.8f, 3.14159265358979323846f};

    // ---- stage X (300 rows x 32) ----
    for (int idx = tid; idx < 300 * 32; idx += NTHREADS) {
        int t   = idx / 3200;
        int rem = idx - t * 3200;
        int r = rem >> 5;
        int c = rem & 31;
        const float* Asrc = (t == 0) ? Av : ((t == 1) ? Aa : Ap);
        sm[OFF_X4 + (t * NUMR + r) * 32 + c] = Asrc[r * NVAR + c];
    }
    __syncthreads();

    // ---- G = sum_t X_t^T X_t ----
    {
        int a = warp;
        int b = lane;
        float g0 = 0.f, g1 = 0.f;
        for (int g = 0; g < 300; g++) {
            float xb  = sm[OFF_X4 + g * 32 + b];
            g0 += sm[OFF_X4 + g * 32 + a] * xb;
            g1 += sm[OFF_X4 + g * 32 + a + 16] * xb;
        }
        sm[OFF_G + a * 32 + b]        = g0;
        sm[OFF_G + (a + 16) * 32 + b] = g1;
    }

    // ---- per-sample state ----
    float cin[3], cprev[3], l[3][3], sdl[3];
#pragma unroll
    for (int m = 0; m < 3; m++) {
        int j = (mb + m) * 32 + lane;
        cin[m]   = c_in_g[s * NVAR + j];
        cprev[m] = c_samp[s * NVAR + j];
    }
#pragma unroll
    for (int t = 0; t < 3; t++)
#pragma unroll
        for (int m = 0; m < 3; m++)
            l[t][m] = lamda[s * (3 * NVAR) + t * NVAR + (mb + m) * 32 + lane];

    float pbq[3];
#pragma unroll
    for (int jg = 0; jg < 3; jg++) {
        int j = bj0 + jg * 4;
        float a = 0.f;
        const float* bq = b_eq + (blockIdx.x * SPB + bs) * NEQC;
        for (int k = 0; k < NEQC; k++)
            a += Qi[j * NHDIM + NVAR + k] * bq[k];
        pbq[jg] = a;
    }

    // stage initial P (p0 = c_samp)
#pragma unroll
    for (int m = 0; m < 3; m++)
        sm[OFF_P + (col0 + m) * 36 + lane] = cprev[m];
    __syncthreads();   // X, G, P ready

    // ---- D0: row-parallel y0/w0 ----
    {
        ull PA[16], PB[16];
        const ulonglong2* PcA = (const ulonglong2*)&sm[OFF_P + lane * 36];
        const ulonglong2* PcB = (const ulonglong2*)&sm[OFF_P + (32 + (lane & 15)) * 36];
#pragma unroll
        for (int q = 0; q < 8; q++) {
            ulonglong2 a = PcA[q]; PA[2*q] = a.x; PA[2*q+1] = a.y;
            ulonglong2 b = PcB[q]; PB[2*q] = b.x; PB[2*q+1] = b.y;
        }
#pragma unroll
        for (int t = 0; t < 3; t++) {
            float V = Vb[t];
#pragma unroll
            for (int i = 0; i < 7; i++) {
                int r = warp + 16 * i;
                if (r < NUMR) {
                    const ulonglong2* Xr = (const ulonglong2*)&sm[OFF_X4 + (t * NUMR + r) * 32];
                    ull aA = 0, aB = 0;
#pragma unroll
                    for (int q = 0; q < 8; q++) {
                        ulonglong2 x = Xr[q];
                        fma2(aA, x.x, PA[2*q]); fma2(aA, x.y, PA[2*q+1]);
                        fma2(aB, x.x, PB[2*q]); fma2(aB, x.y, PB[2*q+1]);
                    }
                    float ynA = hadd2(aA), ynB = hadd2(aB);
                    int base = t * 4800 + r * 48;
                    sm[OFF_Y + base + lane] = ynA;
                    sm[OFF_W + base + lane] = fmaxf(ynA - V, 0.f) - fmaxf(-ynA - V, 0.f);
                    if (lane < 16) {
                        sm[OFF_Y + base + 32 + lane] = ynB;
                        sm[OFF_W + base + 32 + lane] = fmaxf(ynB - V, 0.f) - fmaxf(-ynB - V, 0.f);
                    }
                }
            }
        }
    }
    __syncthreads();

    // ---- E0: dl0 ----
    if (warp < 12) {
        int t  = warp >> 2;
        int k0 = (warp & 3) * 8;
        ull dA[4] = {0,0,0,0}, dB[4] = {0,0,0,0};
        for (int r = 0; r < NUMR; r++) {
            const ulonglong2* Xr = (const ulonglong2*)&sm[OFF_X4 + (t * NUMR + r) * 32 + k0];
            int wbase = OFF_W + t * 4800 + r * 48;
            ull wpA = pack2(sm[wbase + lane]);
            ull wpB = pack2(sm[wbase + 32 + (lane & 15)]);
            ulonglong2 x0 = Xr[0], x1 = Xr[1];
            fma2(dA[0], x0.x, wpA); fma2(dA[1], x0.y, wpA);
            fma2(dA[2], x1.x, wpA); fma2(dA[3], x1.y, wpA);
            fma2(dB[0], x0.x, wpB); fma2(dB[1], x0.y, wpB);
            fma2(dB[2], x1.x, wpB); fma2(dB[3], x1.y, wpB);
        }
#pragma unroll
        for (int j = 0; j < 4; j++) {
            float lo, hi;
            unpack2(lo, hi, dA[j]);
            sm[OFF_DL + (t * 32 + k0 + 2*j    ) * 49 + lane] = lo;
            sm[OFF_DL + (t * 32 + k0 + 2*j + 1) * 49 + lane] = hi;
            if (lane < 16) {
                unpack2(lo, hi, dB[j]);
                sm[OFF_DL + (t * 32 + k0 + 2*j    ) * 49 + 32 + lane] = lo;
                sm[OFF_DL + (t * 32 + k0 + 2*j + 1) * 49 + 32 + lane] = hi;
            }
        }
    }
    __syncthreads();

    // ---- sdl0 ----
#pragma unroll
    for (int m = 0; m < 3; m++) sdl[m] = 0.f;
#pragma unroll
    for (int t = 0; t < 3; t++)
#pragma unroll
        for (int m = 0; m < 3; m++)
            sdl[m] += sm[OFF_DL + (t * 32 + lane) * 49 + col0 + m];

    float fp_sum = 0.f, rp_sum = 0.f;

    const int j0 = (bj0    ) * 48;   // row offsets in 16B units (row stride 192 fl = 48 u2x2)
    const int j1 = (bj0 + 4) * 48;
    const int j2 = (bj0 + 8) * 48;

    for (int it = 0; it < MAXIT; it++) {
        // ======== A: gp = G@p ; rhs ========
        {
            const float* Gm = &sm[OFF_G];
            const float* P0 = &sm[OFF_P + col0 * 36];
            const float* P1 = P0 + 36;
            const float* P2 = P0 + 72;
            float g0 = 0.f, g1 = 0.f, g2 = 0.f;
#pragma unroll 8
            for (int k = 0; k < 32; k++) {
                float gk = Gm[k * 32 + lane];
                g0 += gk * P0[k]; g1 += gk * P1[k]; g2 += gk * P2[k];
            }
            float gpv[3] = {g0, g1, g2};
#pragma unroll
            for (int m = 0; m < 3; m++)
                sm[OFF_RHS + samp * 196 + (mb + m) * 32 + lane] =
                    l[0][m] + l[1][m] + l[2][m] + cin[m] + 2.f * gpv[m] - sdl[m];
        }
        __syncthreads();   // rhs ready

        // ======== B: primal = Qpad @ rhs + pb (per-lane L2 streaming, no barriers) ========
        {
            const ulonglong2* Qp = (const ulonglong2*)Qpad;
            const ulonglong2* RV = (const ulonglong2*)&sm[OFF_RHS + bs * 196];
            ull a00 = 0, a01 = 0, a10 = 0, a11 = 0, a20 = 0, a21 = 0;
#pragma unroll 4
            for (int kk = 0; kk < 48; kk++) {
                ulonglong2 q0 = Qp[j0 + kk];
                ulonglong2 q1 = Qp[j1 + kk];
                ulonglong2 q2 = Qp[j2 + kk];
                ulonglong2 rv = RV[kk];
                fma2(a00, q0.x, rv.x); fma2(a01, q0.y, rv.y);
                fma2(a10, q1.x, rv.x); fma2(a11, q1.y, rv.y);
                fma2(a20, q2.x, rv.x); fma2(a21, q2.y, rv.y);
            }
            float p0 = hadd2(a00) + hadd2(a01) + pbq[0];
            float p1 = hadd2(a10) + hadd2(a11) + pbq[1];
            float p2 = hadd2(a20) + hadd2(a21) + pbq[2];
            int ja = bj0, jb = bj0 + 4, jc = bj0 + 8;
            sm[OFF_P + (bs * 6 + (ja >> 5)) * 36 + (ja & 31)] = p0;
            sm[OFF_P + (bs * 6 + (jb >> 5)) * 36 + (jb & 31)] = p1;
            sm[OFF_P + (bs * 6 + (jc >> 5)) * 36 + (jc & 31)] = p2;
        }
        __syncthreads();   // P_new ready

        // ======== C: dc ========
        float dc = 0.f;
#pragma unroll
        for (int m = 0; m < 3; m++) {
            float pr = sm[OFF_P + (col0 + m) * 36 + lane];
            float dd = pr - cprev[m];
            dc += dd * dd;
            cprev[m] = pr;
        }

        // ======== D: row-parallel y/w + res/ds partials ========
        {
            ull PA[16], PB[16];
            const ulonglong2* PcA = (const ulonglong2*)&sm[OFF_P + lane * 36];
            const ulonglong2* PcB = (const ulonglong2*)&sm[OFF_P + (32 + (lane & 15)) * 36];
#pragma unroll
            for (int q = 0; q < 8; q++) {
                ulonglong2 a = PcA[q]; PA[2*q] = a.x; PA[2*q+1] = a.y;
                ulonglong2 b = PcB[q]; PB[2*q] = b.x; PB[2*q+1] = b.y;
            }
#pragma unroll
            for (int t = 0; t < 3; t++) {
                float V = Vb[t];
                float raA = 0.f, daA = 0.f, raB = 0.f, daB = 0.f;
#pragma unroll
                for (int i = 0; i < 7; i++) {
                    int r = warp + 16 * i;
                    if (r < NUMR) {
                        const ulonglong2* Xr = (const ulonglong2*)&sm[OFF_X4 + (t * NUMR + r) * 32];
                        ull aA = 0, aB = 0;
#pragma unroll
                        for (int q = 0; q < 8; q++) {
                            ulonglong2 x = Xr[q];
                            fma2(aA, x.x, PA[2*q]); fma2(aA, x.y, PA[2*q+1]);
                            fma2(aB, x.x, PB[2*q]); fma2(aB, x.y, PB[2*q+1]);
                        }
                        float ynA = hadd2(aA), ynB = hadd2(aB);
                        int base = t * 4800 + r * 48;
                        float yoA = sm[OFF_Y + base + lane];
                        float rtA = fmaxf(ynA - V, 0.f);
                        float rbA = fmaxf(-ynA - V, 0.f);
                        raA += rtA * rtA + rbA * rbA;
                        float d1 = fmaxf(V - ynA, 0.f) - fmaxf(V - yoA, 0.f);
                        float d2 = fmaxf(V + ynA, 0.f) - fmaxf(V + yoA, 0.f);
                        daA += d1 * d1 + d2 * d2;
                        sm[OFF_Y + base + lane] = ynA;
                        sm[OFF_W + base + lane] = rtA - rbA;
                        if (lane < 16) {
                            float yoB = sm[OFF_Y + base + 32 + lane];
                            float rtB = fmaxf(ynB - V, 0.f);
                            float rbB = fmaxf(-ynB - V, 0.f);
                            raB += rtB * rtB + rbB * rbB;
                            float e1 = fmaxf(V - ynB, 0.f) - fmaxf(V - yoB, 0.f);
                            float e2 = fmaxf(V + ynB, 0.f) - fmaxf(V + yoB, 0.f);
                            daB += e1 * e1 + e2 * e2;
                            sm[OFF_Y + base + 32 + lane] = ynB;
                            sm[OFF_W + base + 32 + lane] = rtB - rbB;
                        }
                    }
                }
                sm[OFF_PART + ((0 * 3 + t) * 16 + warp) * 49 + lane] = raA;
                sm[OFF_PART + ((1 * 3 + t) * 16 + warp) * 49 + lane] = daA;
                if (lane < 16) {
                    sm[OFF_PART + ((0 * 3 + t) * 16 + warp) * 49 + 32 + lane] = raB;
                    sm[OFF_PART + ((1 * 3 + t) * 16 + warp) * 49 + 32 + lane] = daB;
                }
            }
        }
        __syncthreads();

        // ======== E: dl = X^T w ========
        if (warp < 12) {
            int t  = warp >> 2;
            int k0 = (warp & 3) * 8;
            ull dA[4] = {0,0,0,0}, dB[4] = {0,0,0,0};
            for (int r = 0; r < NUMR; r++) {
                const ulonglong2* Xr = (const ulonglong2*)&sm[OFF_X4 + (t * NUMR + r) * 32 + k0];
                int wbase = OFF_W + t * 4800 + r * 48;
                ull wpA = pack2(sm[wbase + lane]);
                ull wpB = pack2(sm[wbase + 32 + (lane & 15)]);
                ulonglong2 x0 = Xr[0], x1 = Xr[1];
                fma2(dA[0], x0.x, wpA); fma2(dA[1], x0.y, wpA);
                fma2(dA[2], x1.x, wpA); fma2(dA[3], x1.y, wpA);
                fma2(dB[0], x0.x, wpB); fma2(dB[1], x0.y, wpB);
                fma2(dB[2], x1.x, wpB); fma2(dB[3], x1.y, wpB);
            }
#pragma unroll
            for (int j = 0; j < 4; j++) {
                float lo, hi;
                unpack2(lo, hi, dA[j]);
                sm[OFF_DL + (t * 32 + k0 + 2*j    ) * 49 + lane] = lo;
                sm[OFF_DL + (t * 32 + k0 + 2*j + 1) * 49 + lane] = hi;
                if (lane < 16) {
                    unpack2(lo, hi, dB[j]);
                    sm[OFF_DL + (t * 32 + k0 + 2*j    ) * 49 + 32 + lane] = lo;
                    sm[OFF_DL + (t * 32 + k0 + 2*j + 1) * 49 + 32 + lane] = hi;
                }
            }
        }
        __syncthreads();

        // ======== F: lambda update, sdl, norms ========
        float dln[3];
#pragma unroll
        for (int m = 0; m < 3; m++) sdl[m] = 0.f;
#pragma unroll
        for (int t = 0; t < 3; t++) {
            float dls = 0.f;
#pragma unroll
            for (int m = 0; m < 3; m++) {
                float dl = sm[OFF_DL + (t * 32 + lane) * 49 + col0 + m];
                l[t][m] -= dl;
                sdl[m]  += dl;
                dls += dl * dl;
            }
            dln[t] = dls;
        }
        float rds[6];
#pragma unroll
        for (int q = 0; q < 6; q++) {
            float v = 0.f;
            if (lane < 16) {
                int base = OFF_PART + (q * 16 + lane) * 49 + col0;
                v = sm[base] + sm[base + 1] + sm[base + 2];
            }
            rds[q] = v;
        }

        float red[10] = {rds[0], rds[1], rds[2],
                         rds[3], rds[4], rds[5],
                         dln[0], dln[1], dln[2], dc};
#pragma unroll
        for (int off = 16; off; off >>= 1)
#pragma unroll
            for (int q = 0; q < 10; q++)
                red[q] += __shfl_xor_sync(0xffffffffu, red[q], off);

        if (lane == 0) {
#pragma unroll
            for (int q = 0; q < 10; q++)
                sm[OFF_RED + warp * 12 + q] = red[q];
        }
        __syncthreads();
        {
            int wp = warp ^ 1;
            float tot[10];
#pragma unroll
            for (int q = 0; q < 10; q++)
                tot[q] = sm[OFF_RED + warp * 12 + q] + sm[OFF_RED + wp * 12 + q];
            rp_sum += sqrtf(tot[0]) + sqrtf(tot[1]) + sqrtf(tot[2]);
            fp_sum += sqrtf(tot[3]) + sqrtf(tot[4]) + sqrtf(tot[5])
                    + sqrtf(tot[6]) + sqrtf(tot[7]) + sqrtf(tot[8]) + sqrtf(tot[9]);
        }
    }

    // ---- outputs ----
#pragma unroll
    for (int m = 0; m < 3; m++)
        out[s * NVAR + (mb + m) * 32 + lane] = cprev[m];
    if (h == 0 && lane == 0) {
        out[BATCH * NVAR + s]         = fp_sum * (1.0f / MAXIT);
        out[BATCH * NVAR + BATCH + s] = rp_sum * (1.0f / MAXIT);
    }
}

extern "C" void kernel_launch(void* const* d_in, const int* in_sizes, int n_in,
                              void* d_out, int out_size)
{
    const float* lamda = (const float*)d_in[0];
    const float* c_in  = (const float*)d_in[1];
    const float* c_s   = (const float*)d_in[2];
    const float* b_eq  = (const float*)d_in[3];
    const float* Av    = (const float*)d_in[4];
    const float* Aa    = (const float*)d_in[5];
    const float* Ap    = (const float*)d_in[6];
    const float* Qi    = (const float*)d_in[7];
    float* out = (float*)d_out;

    qprep_kernel<<<(NVAR * NVAR + 255) / 256, 256>>>(Qi);

    int smem_bytes = SMEM_FLOATS * sizeof(float);
    cudaFuncSetAttribute(proj_filter_kernel,
                         cudaFuncAttributeMaxDynamicSharedMemorySize, smem_bytes);
    proj_filter_kernel<<<BATCH / SPB, NTHREADS, smem_bytes>>>(
        lamda, c_in, c_s, b_eq, Av, Aa, Ap, Qi, out);
}